// round 8
// baseline (speedup 1.0000x reference)
#include <cuda_runtime.h>
#include <cstdint>

// HyperConnections, round 8: 4 CTAs/SM (64-reg fit via smem stash of streams
// 2,3) + parallel 16-block precompute.
// Identity: dot(norm_h, w) = rstd*(sum h*g*w - mu*sum g*w) + sum beta_ln*w

using u64 = unsigned long long;

constexpr int DIMC  = 2048;
constexpr int RATEC = 4;
constexpr int NW    = 5;      // alpha cols 1..4 (col 0 unused by output) + beta_fn
constexpr int TPB   = 256;
constexpr float DSCALE = 0.01f;
constexpr float EPSF   = 1e-5f;

__device__ float g_W[NW][DIMC];   // gamma[d] * w_j[d]
__device__ float g_S1[NW];        // sum gamma*w
__device__ float g_S2[NW];        // sum ln_beta*w

// ---- f32x2 packed helpers (sm_10x) ----
__device__ __forceinline__ u64 f2add(u64 a, u64 b) {
    u64 r; asm("add.rn.f32x2 %0,%1,%2;" : "=l"(r) : "l"(a), "l"(b)); return r;
}
__device__ __forceinline__ u64 f2mul(u64 a, u64 b) {
    u64 r; asm("mul.rn.f32x2 %0,%1,%2;" : "=l"(r) : "l"(a), "l"(b)); return r;
}
__device__ __forceinline__ u64 f2fma(u64 a, u64 b, u64 c) {
    u64 r; asm("fma.rn.f32x2 %0,%1,%2,%3;" : "=l"(r) : "l"(a), "l"(b), "l"(c)); return r;
}
__device__ __forceinline__ float f2hadd(u64 a) {
    float lo, hi; asm("mov.b64 {%0,%1},%2;" : "=f"(lo), "=f"(hi) : "l"(a));
    return lo + hi;
}
__device__ __forceinline__ void f2unpack(u64 a, float& lo, float& hi) {
    asm("mov.b64 {%0,%1},%2;" : "=f"(lo), "=f"(hi) : "l"(a));
}
__device__ __forceinline__ u64 f2bcast(float v) {
    u64 r; asm("mov.b64 %0,{%1,%1};" : "=l"(r) : "f"(v)); return r;
}
__device__ __forceinline__ void ldg2(const float* p, u64& a, u64& b) {
    asm("ld.global.nc.v2.u64 {%0,%1},[%2];" : "=l"(a), "=l"(b) : "l"(p));
}
__device__ __forceinline__ void stg2(float* p, u64 a, u64 b) {
    asm("st.global.v2.u64 [%0],{%1,%2};" :: "l"(p), "l"(a), "l"(b));
}

// 16 blocks: each redundantly computes S1/S2 (L2-hot reads) and writes its
// own 128-dim slice of g_W. All blocks write identical S1/S2 values.
__global__ void precompute_k(const float* __restrict__ gamma,
                             const float* __restrict__ lbeta,
                             const float* __restrict__ afn,   // (DIM,5)
                             const float* __restrict__ bfn) {
    const int tid = threadIdx.x;        // 256
    const int blk = blockIdx.x;         // 16
    float s1[NW], s2[NW];
#pragma unroll
    for (int j = 0; j < NW; j++) { s1[j] = 0.f; s2[j] = 0.f; }
    for (int d = tid; d < DIMC; d += TPB) {
        const float g = gamma[d], b = lbeta[d];
        const bool mine = ((d >> 7) == blk);       // 128-dim slice ownership
#pragma unroll
        for (int j = 0; j < NW; j++) {
            const float w = (j < 4) ? afn[d * 5 + j + 1] : bfn[d];
            if (mine) g_W[j][d] = g * w;
            s1[j] += g * w;
            s2[j] += b * w;
        }
    }
#pragma unroll
    for (int j = 0; j < NW; j++) {
#pragma unroll
        for (int o = 16; o; o >>= 1) {
            s1[j] += __shfl_xor_sync(0xffffffffu, s1[j], o);
            s2[j] += __shfl_xor_sync(0xffffffffu, s2[j], o);
        }
    }
    __shared__ float sm[8][2 * NW];
    const int w = tid >> 5, lane = tid & 31;
    if (lane == 0) {
#pragma unroll
        for (int j = 0; j < NW; j++) { sm[w][j] = s1[j]; sm[w][NW + j] = s2[j]; }
    }
    __syncthreads();
    if (tid < 2 * NW) {
        float s = 0.f;
#pragma unroll
        for (int ww = 0; ww < 8; ww++) s += sm[ww][tid];
        if (tid < NW) g_S1[tid] = s;               // identical value from all blocks
        else          g_S2[tid - NW] = s;
    }
}

__global__ __launch_bounds__(TPB, 4) void hyper_k(
    const float* __restrict__ h,    // (NTOK, RATE, DIM)
    const float* __restrict__ h_o,  // (NTOK, DIM)
    const float* __restrict__ sA,   // (RATE, 5)
    const float* __restrict__ sB,   // (RATE,)
    float* __restrict__ out)        // (NTOK, RATE, DIM)
{
    __shared__ __align__(16) float s_h23[2 * DIMC];   // streams 2,3 stash (16 KB)
    __shared__ float s_rows[64][28];                  // per-(warp,lane-class) partials
    __shared__ float s_fin[28];
    __shared__ __align__(16) u64 s_ab[RATEC * 6];     // [n*6+m]: m<4 alpha, 4=beta

    const int tid  = threadIdx.x;
    const int lane = tid & 31, w = tid >> 5;
    const int t    = blockIdx.x;
    const size_t hb = (size_t)t * (RATEC * DIMC);
    const int i0 = tid * 4;                     // dims [i0, i0+4)
    const int i1 = (DIMC / 2) + tid * 4;        // dims [i1, i1+4)

    float r[28];                                // r[m*7 + {0:sum,1:sum2,2..6:dots}]

    // ---- Phase 1a: streams 2,3 -> stats + dots, then stash to smem ----
    {
        u64 h2[4], h3[4];
        {
            const float* b2 = h + hb + 2 * DIMC;
            const float* b3 = h + hb + 3 * DIMC;
            ldg2(b2 + i0, h2[0], h2[1]);  ldg2(b2 + i1, h2[2], h2[3]);
            ldg2(b3 + i0, h3[0], h3[1]);  ldg2(b3 + i1, h3[2], h3[3]);
        }
        u64 s2v = f2add(f2add(h2[0], h2[1]), f2add(h2[2], h2[3]));
        u64 q2v = f2fma(h2[0], h2[0], f2fma(h2[1], h2[1],
                  f2fma(h2[2], h2[2], f2mul(h2[3], h2[3]))));
        u64 s3v = f2add(f2add(h3[0], h3[1]), f2add(h3[2], h3[3]));
        u64 q3v = f2fma(h3[0], h3[0], f2fma(h3[1], h3[1],
                  f2fma(h3[2], h3[2], f2mul(h3[3], h3[3]))));
        r[2*7+0] = f2hadd(s2v);  r[2*7+1] = f2hadd(q2v);
        r[3*7+0] = f2hadd(s3v);  r[3*7+1] = f2hadd(q3v);
#pragma unroll
        for (int j = 0; j < NW; j++) {
            u64 w0, w1, w2, w3;
            ldg2(&g_W[j][i0], w0, w1);
            ldg2(&g_W[j][i1], w2, w3);
            u64 d2 = f2fma(h2[0], w0, f2fma(h2[1], w1,
                     f2fma(h2[2], w2, f2mul(h2[3], w3))));
            u64 d3 = f2fma(h3[0], w0, f2fma(h3[1], w1,
                     f2fma(h3[2], w2, f2mul(h3[3], w3))));
            r[2*7+2+j] = f2hadd(d2);
            r[3*7+2+j] = f2hadd(d3);
        }
        // stash (each thread only ever reads back its own slice)
        *(ulonglong2*)&s_h23[0*DIMC + i0] = make_ulonglong2(h2[0], h2[1]);
        *(ulonglong2*)&s_h23[0*DIMC + i1] = make_ulonglong2(h2[2], h2[3]);
        *(ulonglong2*)&s_h23[1*DIMC + i0] = make_ulonglong2(h3[0], h3[1]);
        *(ulonglong2*)&s_h23[1*DIMC + i1] = make_ulonglong2(h3[2], h3[3]);
    }

    // ---- Phase 1b: streams 0,1 -> stats + dots, kept in registers ----
    u64 hr01[2][4];
#pragma unroll
    for (int n = 0; n < 2; n++) {
        const float* base = h + hb + n * DIMC;
        ldg2(base + i0, hr01[n][0], hr01[n][1]);
        ldg2(base + i1, hr01[n][2], hr01[n][3]);
        u64 s = f2add(f2add(hr01[n][0], hr01[n][1]), f2add(hr01[n][2], hr01[n][3]));
        u64 q = f2fma(hr01[n][0], hr01[n][0], f2fma(hr01[n][1], hr01[n][1],
                f2fma(hr01[n][2], hr01[n][2], f2mul(hr01[n][3], hr01[n][3]))));
        r[n*7+0] = f2hadd(s);
        r[n*7+1] = f2hadd(q);
    }
#pragma unroll
    for (int j = 0; j < NW; j++) {
        u64 w0, w1, w2, w3;
        ldg2(&g_W[j][i0], w0, w1);              // L1-hot
        ldg2(&g_W[j][i1], w2, w3);
#pragma unroll
        for (int n = 0; n < 2; n++) {
            u64 d = f2fma(hr01[n][0], w0, f2fma(hr01[n][1], w1,
                    f2fma(hr01[n][2], w2, f2mul(hr01[n][3], w3))));
            r[n*7+2+j] = f2hadd(d);
        }
    }

    // ---- 2-level butterfly: lane L sums over {L, L^8, L^16, L^24} ----
#pragma unroll
    for (int v = 0; v < 28; v++) r[v] += __shfl_xor_sync(0xffffffffu, r[v], 16);
#pragma unroll
    for (int v = 0; v < 28; v++) r[v] += __shfl_xor_sync(0xffffffffu, r[v], 8);

    if (lane < 8) {
        const int row = w * 8 + lane;           // 64 disjoint partial rows
#pragma unroll
        for (int k = 0; k < 7; k++)
            *(float4*)&s_rows[row][k * 4] =
                make_float4(r[k*4], r[k*4+1], r[k*4+2], r[k*4+3]);
    }

    // ---- Prefetch h_o: DRAM latency overlaps reduction + barriers ----
    u64 ho[4];
    {
        const float* ob = h_o + (size_t)t * DIMC;
        ldg2(ob + i0, ho[0], ho[1]);
        ldg2(ob + i1, ho[2], ho[3]);
    }
    __syncthreads();

    // ---- Warp 0: final reduce (packed), then alpha/beta once ----
    if (w == 0) {
        if (tid < 14) {
            u64 a0 = 0ull, a1 = 0ull;
#pragma unroll
            for (int rr = 0; rr < 32; rr++) {
                a0 = f2add(a0, *(const u64*)&s_rows[2*rr    ][2*tid]);
                a1 = f2add(a1, *(const u64*)&s_rows[2*rr + 1][2*tid]);
            }
            float lo, hi; f2unpack(f2add(a0, a1), lo, hi);
            s_fin[2*tid] = lo; s_fin[2*tid + 1] = hi;
        }
        __syncwarp();
        if (tid < 20) {
            const int m  = (tid < 16) ? (tid >> 2) : (tid - 16);
            const int jj = (tid < 16) ? (tid & 3) : 4;
            const float invD = 1.0f / DIMC;
            const float mu   = s_fin[m * 7 + 0] * invD;
            const float var  = s_fin[m * 7 + 1] * invD - mu * mu;
            const float rstd = rsqrtf(var + EPSF);
            const float dot  = rstd * (s_fin[m * 7 + 2 + jj] - mu * g_S1[jj]) + g_S2[jj];
            const float v    = dot * DSCALE +
                               ((tid < 16) ? sA[m * 5 + jj + 1] : sB[m]);
            if (tid < 16) s_ab[jj * 6 + m] = f2bcast(v);   // alpha[m][n=jj]
            else          s_ab[m * 6 + 4]  = f2bcast(v);   // beta[n=m]
        }
    }
    __syncthreads();

    // ---- Phase 2: mix + depth connection ----
#pragma unroll
    for (int n = 0; n < RATEC; n++) {
        const ulonglong2 q0 = *(const ulonglong2*)&s_ab[n * 6 + 0];  // alpha[0..1][n]
        const ulonglong2 q1 = *(const ulonglong2*)&s_ab[n * 6 + 2];  // alpha[2..3][n]
        const u64 bn = s_ab[n * 6 + 4];                              // beta[n]
        const ulonglong2 h2a = *(const ulonglong2*)&s_h23[0*DIMC + i0];
        const ulonglong2 h2b = *(const ulonglong2*)&s_h23[0*DIMC + i1];
        const ulonglong2 h3a = *(const ulonglong2*)&s_h23[1*DIMC + i0];
        const ulonglong2 h3b = *(const ulonglong2*)&s_h23[1*DIMC + i1];
        const u64 h2v[4] = {h2a.x, h2a.y, h2b.x, h2b.y};
        const u64 h3v[4] = {h3a.x, h3a.y, h3b.x, h3b.y};
        u64 o[4];
#pragma unroll
        for (int i = 0; i < 4; i++) {
            u64 a2 = f2mul(ho[i], bn);
            a2 = f2fma(hr01[0][i], q0.x, a2);
            a2 = f2fma(hr01[1][i], q0.y, a2);
            a2 = f2fma(h2v[i],     q1.x, a2);
            a2 = f2fma(h3v[i],     q1.y, a2);
            o[i] = a2;
        }
        float* dst = out + hb + n * DIMC;
        stg2(dst + i0, o[0], o[1]);
        stg2(dst + i1, o[2], o[3]);
    }
}

extern "C" void kernel_launch(void* const* d_in, const int* in_sizes, int n_in,
                              void* d_out, int out_size) {
    const float* h     = (const float*)d_in[0];
    const float* h_o   = (const float*)d_in[1];
    const float* gamma = (const float*)d_in[2];
    const float* lbeta = (const float*)d_in[3];
    const float* afn   = (const float*)d_in[4];
    const float* bfn   = (const float*)d_in[5];
    const float* sA    = (const float*)d_in[6];
    const float* sB    = (const float*)d_in[7];
    float* out = (float*)d_out;

    const int ntok = in_sizes[1] / DIMC;   // b*l from h_o element count

    precompute_k<<<16, TPB>>>(gamma, lbeta, afn, bfn);
    hyper_k<<<ntok, TPB>>>(h, h_o, sA, sB, out);
}

// round 9
// speedup vs baseline: 1.2853x; 1.2853x over previous
#include <cuda_runtime.h>
#include <cstdint>

// HyperConnections, round 9: R7 structure (front-batched register loads,
// 3 CTAs/SM) + parallelized final reduce + hoisted static-param loads.
// Identity: dot(norm_h, w) = rstd*(sum h*g*w - mu*sum g*w) + sum beta_ln*w

using u64 = unsigned long long;

constexpr int DIMC  = 2048;
constexpr int RATEC = 4;
constexpr int NW    = 5;      // alpha cols 1..4 (col 0 unused by output) + beta_fn
constexpr int TPB   = 256;
constexpr float DSCALE = 0.01f;
constexpr float EPSF   = 1e-5f;

__device__ float g_W[NW][DIMC];   // gamma[d] * w_j[d]
__device__ float g_S1[NW];        // sum gamma*w
__device__ float g_S2[NW];        // sum ln_beta*w

// ---- f32x2 packed helpers (sm_10x) ----
__device__ __forceinline__ u64 f2add(u64 a, u64 b) {
    u64 r; asm("add.rn.f32x2 %0,%1,%2;" : "=l"(r) : "l"(a), "l"(b)); return r;
}
__device__ __forceinline__ u64 f2mul(u64 a, u64 b) {
    u64 r; asm("mul.rn.f32x2 %0,%1,%2;" : "=l"(r) : "l"(a), "l"(b)); return r;
}
__device__ __forceinline__ u64 f2fma(u64 a, u64 b, u64 c) {
    u64 r; asm("fma.rn.f32x2 %0,%1,%2,%3;" : "=l"(r) : "l"(a), "l"(b), "l"(c)); return r;
}
__device__ __forceinline__ float f2hadd(u64 a) {
    float lo, hi; asm("mov.b64 {%0,%1},%2;" : "=f"(lo), "=f"(hi) : "l"(a));
    return lo + hi;
}
__device__ __forceinline__ u64 f2bcast(float v) {
    u64 r; asm("mov.b64 %0,{%1,%1};" : "=l"(r) : "f"(v)); return r;
}
__device__ __forceinline__ void ldg2(const float* p, u64& a, u64& b) {
    asm("ld.global.nc.v2.u64 {%0,%1},[%2];" : "=l"(a), "=l"(b) : "l"(p));
}
__device__ __forceinline__ void stg2(float* p, u64 a, u64 b) {
    asm("st.global.v2.u64 [%0],{%1,%2};" :: "l"(p), "l"(a), "l"(b));
}

// 16 blocks: each redundantly computes S1/S2 (L2-hot reads) and writes its
// own 128-dim slice of g_W. All blocks write identical S1/S2 values.
__global__ void precompute_k(const float* __restrict__ gamma,
                             const float* __restrict__ lbeta,
                             const float* __restrict__ afn,   // (DIM,5)
                             const float* __restrict__ bfn) {
    const int tid = threadIdx.x;        // 256
    const int blk = blockIdx.x;         // 16
    float s1[NW], s2[NW];
#pragma unroll
    for (int j = 0; j < NW; j++) { s1[j] = 0.f; s2[j] = 0.f; }
    for (int d = tid; d < DIMC; d += TPB) {
        const float g = gamma[d], b = lbeta[d];
        const bool mine = ((d >> 7) == blk);       // 128-dim slice ownership
#pragma unroll
        for (int j = 0; j < NW; j++) {
            const float w = (j < 4) ? afn[d * 5 + j + 1] : bfn[d];
            if (mine) g_W[j][d] = g * w;
            s1[j] += g * w;
            s2[j] += b * w;
        }
    }
#pragma unroll
    for (int j = 0; j < NW; j++) {
#pragma unroll
        for (int o = 16; o; o >>= 1) {
            s1[j] += __shfl_xor_sync(0xffffffffu, s1[j], o);
            s2[j] += __shfl_xor_sync(0xffffffffu, s2[j], o);
        }
    }
    __shared__ float sm[8][2 * NW];
    const int w = tid >> 5, lane = tid & 31;
    if (lane == 0) {
#pragma unroll
        for (int j = 0; j < NW; j++) { sm[w][j] = s1[j]; sm[w][NW + j] = s2[j]; }
    }
    __syncthreads();
    if (tid < 2 * NW) {
        float s = 0.f;
#pragma unroll
        for (int ww = 0; ww < 8; ww++) s += sm[ww][tid];
        if (tid < NW) g_S1[tid] = s;
        else          g_S2[tid - NW] = s;
    }
}

__global__ __launch_bounds__(TPB, 3) void hyper_k(
    const float* __restrict__ h,    // (NTOK, RATE, DIM)
    const float* __restrict__ h_o,  // (NTOK, DIM)
    const float* __restrict__ sA,   // (RATE, 5)
    const float* __restrict__ sB,   // (RATE,)
    float* __restrict__ out)        // (NTOK, RATE, DIM)
{
    __shared__ float s_rows[64][28];            // per-(warp,lane-class) partials
    __shared__ float s_fin[28];
    __shared__ __align__(16) u64 s_ab[RATEC * 6];  // [n*6+m]: m<4 alpha[m][n], 4=beta[n]

    const int tid  = threadIdx.x;
    const int lane = tid & 31, w = tid >> 5;
    const int t    = blockIdx.x;
    const size_t hb = (size_t)t * (RATEC * DIMC);
    const int i0 = tid * 4;                     // dims [i0, i0+4)
    const int i1 = (DIMC / 2) + tid * 4;        // dims [i1, i1+4)

    // Hoisted static params for warp 0 (L2-hot LDG overlapped with phase 1).
    float stat_v = 0.f;
    if (tid < 20)
        stat_v = (tid < 16) ? sA[(tid >> 2) * 5 + (tid & 3) + 1] : sB[tid - 16];

    // ---- Phase 1: load h (4 streams x 4 f32x2 pairs), stats + dots ----
    u64 hr[RATEC][4];
    float r[28];                                // r[m*7 + {0:sum,1:sum2,2..6:dots}]

#pragma unroll
    for (int n = 0; n < RATEC; n++) {
        const float* base = h + hb + n * DIMC;
        ldg2(base + i0, hr[n][0], hr[n][1]);
        ldg2(base + i1, hr[n][2], hr[n][3]);
        u64 s = f2add(f2add(hr[n][0], hr[n][1]), f2add(hr[n][2], hr[n][3]));
        u64 q = f2fma(hr[n][0], hr[n][0],
                f2fma(hr[n][1], hr[n][1],
                f2fma(hr[n][2], hr[n][2],
                f2mul(hr[n][3], hr[n][3]))));
        r[n * 7 + 0] = f2hadd(s);
        r[n * 7 + 1] = f2hadd(q);
    }
#pragma unroll
    for (int j = 0; j < NW; j++) {
        u64 w0, w1, w2, w3;
        ldg2(&g_W[j][i0], w0, w1);              // L1-hot across blocks
        ldg2(&g_W[j][i1], w2, w3);
#pragma unroll
        for (int n = 0; n < RATEC; n++) {
            u64 d = f2fma(hr[n][0], w0,
                    f2fma(hr[n][1], w1,
                    f2fma(hr[n][2], w2,
                    f2mul(hr[n][3], w3))));
            r[n * 7 + 2 + j] = f2hadd(d);
        }
    }

    // ---- 2-level butterfly: lane L ends with sum over {L, L^8, L^16, L^24} ----
#pragma unroll
    for (int v = 0; v < 28; v++) r[v] += __shfl_xor_sync(0xffffffffu, r[v], 16);
#pragma unroll
    for (int v = 0; v < 28; v++) r[v] += __shfl_xor_sync(0xffffffffu, r[v], 8);

    if (lane < 8) {
        const int row = w * 8 + lane;           // 64 disjoint partial rows
#pragma unroll
        for (int k = 0; k < 7; k++)
            *(float4*)&s_rows[row][k * 4] =
                make_float4(r[k*4], r[k*4+1], r[k*4+2], r[k*4+3]);
    }

    // ---- Prefetch h_o NOW: DRAM latency overlaps reduction + barriers ----
    u64 ho[4];
    {
        const float* ob = h_o + (size_t)t * DIMC;
        ldg2(ob + i0, ho[0], ho[1]);
        ldg2(ob + i1, ho[2], ho[3]);
    }
    __syncthreads();

    // ---- Warp 0: parallel final reduce (28 threads, 4-way ILP) ----
    if (w == 0) {
        if (lane < 28) {
            float a0 = 0.f, a1 = 0.f, a2 = 0.f, a3 = 0.f;
#pragma unroll
            for (int rr = 0; rr < 64; rr += 4) {
                a0 += s_rows[rr + 0][lane];
                a1 += s_rows[rr + 1][lane];
                a2 += s_rows[rr + 2][lane];
                a3 += s_rows[rr + 3][lane];
            }
            s_fin[lane] = (a0 + a1) + (a2 + a3);
        }
        __syncwarp();
        if (tid < 20) {
            const int m  = (tid < 16) ? (tid >> 2) : (tid - 16);
            const int jj = (tid < 16) ? (tid & 3) : 4;
            const float invD = 1.0f / DIMC;
            const float mu   = s_fin[m * 7 + 0] * invD;
            const float var  = s_fin[m * 7 + 1] * invD - mu * mu;
            const float rstd = rsqrtf(var + EPSF);
            const float dot  = rstd * (s_fin[m * 7 + 2 + jj] - mu * g_S1[jj]) + g_S2[jj];
            const float v    = dot * DSCALE + stat_v;
            // alpha[m][n=jj] at [jj*6+m]; beta[n=m] at [m*6+4]
            if (tid < 16) s_ab[jj * 6 + m] = f2bcast(v);
            else          s_ab[m * 6 + 4]  = f2bcast(v);
        }
    }
    __syncthreads();

    // ---- Phase 2: mix + depth connection; coefficients read per-stream ----
#pragma unroll
    for (int n = 0; n < RATEC; n++) {
        const ulonglong2 q0 = *(const ulonglong2*)&s_ab[n * 6 + 0];  // alpha[0..1][n]
        const ulonglong2 q1 = *(const ulonglong2*)&s_ab[n * 6 + 2];  // alpha[2..3][n]
        const u64 bn = s_ab[n * 6 + 4];                              // beta[n]
        u64 o[4];
#pragma unroll
        for (int i = 0; i < 4; i++) {
            u64 a2 = f2mul(ho[i], bn);
            a2 = f2fma(hr[0][i], q0.x, a2);
            a2 = f2fma(hr[1][i], q0.y, a2);
            a2 = f2fma(hr[2][i], q1.x, a2);
            a2 = f2fma(hr[3][i], q1.y, a2);
            o[i] = a2;
        }
        float* dst = out + hb + n * DIMC;
        stg2(dst + i0, o[0], o[1]);
        stg2(dst + i1, o[2], o[3]);
    }
}

extern "C" void kernel_launch(void* const* d_in, const int* in_sizes, int n_in,
                              void* d_out, int out_size) {
    const float* h     = (const float*)d_in[0];
    const float* h_o   = (const float*)d_in[1];
    const float* gamma = (const float*)d_in[2];
    const float* lbeta = (const float*)d_in[3];
    const float* afn   = (const float*)d_in[4];
    const float* bfn   = (const float*)d_in[5];
    const float* sA    = (const float*)d_in[6];
    const float* sB    = (const float*)d_in[7];
    float* out = (float*)d_out;

    const int ntok = in_sizes[1] / DIMC;   // b*l from h_o element count

    precompute_k<<<16, TPB>>>(gamma, lbeta, afn, bfn);
    hyper_k<<<ntok, TPB>>>(h, h_o, sA, sB, out);
}

// round 10
// speedup vs baseline: 1.4647x; 1.1396x over previous
#include <cuda_runtime.h>
#include <cstdint>

// HyperConnections, round 10: exact R7 hyper_k (proven 88.4us / 79.8% DRAM)
// + validated 16-block parallel precompute + .cs streaming output stores.
// Identity: dot(norm_h, w) = rstd*(sum h*g*w - mu*sum g*w) + sum beta_ln*w

using u64 = unsigned long long;

constexpr int DIMC  = 2048;
constexpr int RATEC = 4;
constexpr int NW    = 5;      // alpha cols 1..4 (col 0 unused by output) + beta_fn
constexpr int TPB   = 256;
constexpr float DSCALE = 0.01f;
constexpr float EPSF   = 1e-5f;

__device__ float g_W[NW][DIMC];   // gamma[d] * w_j[d]
__device__ float g_S1[NW];        // sum gamma*w
__device__ float g_S2[NW];        // sum ln_beta*w

// ---- f32x2 packed helpers (sm_10x) ----
__device__ __forceinline__ u64 f2add(u64 a, u64 b) {
    u64 r; asm("add.rn.f32x2 %0,%1,%2;" : "=l"(r) : "l"(a), "l"(b)); return r;
}
__device__ __forceinline__ u64 f2mul(u64 a, u64 b) {
    u64 r; asm("mul.rn.f32x2 %0,%1,%2;" : "=l"(r) : "l"(a), "l"(b)); return r;
}
__device__ __forceinline__ u64 f2fma(u64 a, u64 b, u64 c) {
    u64 r; asm("fma.rn.f32x2 %0,%1,%2,%3;" : "=l"(r) : "l"(a), "l"(b), "l"(c)); return r;
}
__device__ __forceinline__ float f2hadd(u64 a) {
    float lo, hi; asm("mov.b64 {%0,%1},%2;" : "=f"(lo), "=f"(hi) : "l"(a));
    return lo + hi;
}
__device__ __forceinline__ void f2unpack(u64 a, float& lo, float& hi) {
    asm("mov.b64 {%0,%1},%2;" : "=f"(lo), "=f"(hi) : "l"(a));
}
__device__ __forceinline__ u64 f2bcast(float v) {
    u64 r; asm("mov.b64 %0,{%1,%1};" : "=l"(r) : "f"(v)); return r;
}
__device__ __forceinline__ void ldg2(const float* p, u64& a, u64& b) {
    asm("ld.global.nc.v2.u64 {%0,%1},[%2];" : "=l"(a), "=l"(b) : "l"(p));
}
__device__ __forceinline__ void stg2cs(float* p, u64 a, u64 b) {
    asm("st.global.cs.v2.u64 [%0],{%1,%2};" :: "l"(p), "l"(a), "l"(b));
}

// 16 blocks: each redundantly computes S1/S2 (L2-hot reads) and writes its
// own 128-dim slice of g_W. All blocks write identical S1/S2 values.
__global__ void precompute_k(const float* __restrict__ gamma,
                             const float* __restrict__ lbeta,
                             const float* __restrict__ afn,   // (DIM,5)
                             const float* __restrict__ bfn) {
    const int tid = threadIdx.x;        // 256
    const int blk = blockIdx.x;         // 16
    float s1[NW], s2[NW];
#pragma unroll
    for (int j = 0; j < NW; j++) { s1[j] = 0.f; s2[j] = 0.f; }
    for (int d = tid; d < DIMC; d += TPB) {
        const float g = gamma[d], b = lbeta[d];
        const bool mine = ((d >> 7) == blk);       // 128-dim slice ownership
#pragma unroll
        for (int j = 0; j < NW; j++) {
            const float w = (j < 4) ? afn[d * 5 + j + 1] : bfn[d];
            if (mine) g_W[j][d] = g * w;
            s1[j] += g * w;
            s2[j] += b * w;
        }
    }
#pragma unroll
    for (int j = 0; j < NW; j++) {
#pragma unroll
        for (int o = 16; o; o >>= 1) {
            s1[j] += __shfl_xor_sync(0xffffffffu, s1[j], o);
            s2[j] += __shfl_xor_sync(0xffffffffu, s2[j], o);
        }
    }
    __shared__ float sm[8][2 * NW];
    const int w = tid >> 5, lane = tid & 31;
    if (lane == 0) {
#pragma unroll
        for (int j = 0; j < NW; j++) { sm[w][j] = s1[j]; sm[w][NW + j] = s2[j]; }
    }
    __syncthreads();
    if (tid < 2 * NW) {
        float s = 0.f;
#pragma unroll
        for (int ww = 0; ww < 8; ww++) s += sm[ww][tid];
        if (tid < NW) g_S1[tid] = s;
        else          g_S2[tid - NW] = s;
    }
}

__global__ __launch_bounds__(TPB, 3) void hyper_k(
    const float* __restrict__ h,    // (NTOK, RATE, DIM)
    const float* __restrict__ h_o,  // (NTOK, DIM)
    const float* __restrict__ sA,   // (RATE, 5)
    const float* __restrict__ sB,   // (RATE,)
    float* __restrict__ out)        // (NTOK, RATE, DIM)
{
    __shared__ float s_rows[64][28];            // per-(warp,lane-class) partials
    __shared__ float s_fin[28];
    __shared__ __align__(16) u64 s_ab[RATEC * 6];  // [n*6+m]: m<4 alpha[m][n], 4=beta[n]

    const int tid  = threadIdx.x;
    const int lane = tid & 31, w = tid >> 5;
    const int t    = blockIdx.x;
    const size_t hb = (size_t)t * (RATEC * DIMC);
    const int i0 = tid * 4;                     // dims [i0, i0+4)
    const int i1 = (DIMC / 2) + tid * 4;        // dims [i1, i1+4)  (dense coalescing)

    // ---- Phase 1: load h (4 streams x 4 f32x2 pairs), stats + dots ----
    u64 hr[RATEC][4];
    float r[28];                                // r[m*7 + {0:sum,1:sum2,2..6:dots}]

#pragma unroll
    for (int n = 0; n < RATEC; n++) {
        const float* base = h + hb + n * DIMC;
        ldg2(base + i0, hr[n][0], hr[n][1]);
        ldg2(base + i1, hr[n][2], hr[n][3]);
        u64 s = f2add(f2add(hr[n][0], hr[n][1]), f2add(hr[n][2], hr[n][3]));
        u64 q = f2fma(hr[n][0], hr[n][0],
                f2fma(hr[n][1], hr[n][1],
                f2fma(hr[n][2], hr[n][2],
                f2mul(hr[n][3], hr[n][3]))));
        r[n * 7 + 0] = f2hadd(s);
        r[n * 7 + 1] = f2hadd(q);
    }
#pragma unroll
    for (int j = 0; j < NW; j++) {
        u64 w0, w1, w2, w3;
        ldg2(&g_W[j][i0], w0, w1);              // L1-hot across blocks
        ldg2(&g_W[j][i1], w2, w3);
#pragma unroll
        for (int n = 0; n < RATEC; n++) {
            u64 d = f2fma(hr[n][0], w0,
                    f2fma(hr[n][1], w1,
                    f2fma(hr[n][2], w2,
                    f2mul(hr[n][3], w3))));
            r[n * 7 + 2 + j] = f2hadd(d);
        }
    }

    // ---- 2-level butterfly: lane L ends with sum over {L, L^8, L^16, L^24} ----
#pragma unroll
    for (int v = 0; v < 28; v++) r[v] += __shfl_xor_sync(0xffffffffu, r[v], 16);
#pragma unroll
    for (int v = 0; v < 28; v++) r[v] += __shfl_xor_sync(0xffffffffu, r[v], 8);

    if (lane < 8) {
        const int row = w * 8 + lane;           // 64 disjoint partial rows
#pragma unroll
        for (int k = 0; k < 7; k++)
            *(float4*)&s_rows[row][k * 4] =
                make_float4(r[k*4], r[k*4+1], r[k*4+2], r[k*4+3]);
    }

    // ---- Prefetch h_o NOW: DRAM latency overlaps reduction + barriers ----
    u64 ho[4];
    {
        const float* ob = h_o + (size_t)t * DIMC;
        ldg2(ob + i0, ho[0], ho[1]);
        ldg2(ob + i1, ho[2], ho[3]);
    }
    __syncthreads();

    // ---- Warp 0: final reduce (packed), then alpha/beta once ----
    if (w == 0) {
        if (tid < 14) {
            u64 a0 = 0ull, a1 = 0ull;           // (0.f,0.f)
#pragma unroll
            for (int rr = 0; rr < 32; rr++) {
                a0 = f2add(a0, *(const u64*)&s_rows[2*rr    ][2*tid]);
                a1 = f2add(a1, *(const u64*)&s_rows[2*rr + 1][2*tid]);
            }
            float lo, hi; f2unpack(f2add(a0, a1), lo, hi);
            s_fin[2*tid] = lo; s_fin[2*tid + 1] = hi;
        }
        __syncwarp();
        if (tid < 20) {
            const int m  = (tid < 16) ? (tid >> 2) : (tid - 16);
            const int jj = (tid < 16) ? (tid & 3) : 4;
            const float invD = 1.0f / DIMC;
            const float mu   = s_fin[m * 7 + 0] * invD;
            const float var  = s_fin[m * 7 + 1] * invD - mu * mu;
            const float rstd = rsqrtf(var + EPSF);
            const float dot  = rstd * (s_fin[m * 7 + 2 + jj] - mu * g_S1[jj]) + g_S2[jj];
            const float v    = dot * DSCALE +
                               ((tid < 16) ? sA[m * 5 + jj + 1] : sB[m]);
            // alpha[m][n=jj] at [jj*6+m]; beta[n=m] at [m*6+4]
            if (tid < 16) s_ab[jj * 6 + m] = f2bcast(v);
            else          s_ab[m * 6 + 4]  = f2bcast(v);
        }
    }
    __syncthreads();

    // ---- Phase 2: mix + depth connection; coefficients read per-stream ----
#pragma unroll
    for (int n = 0; n < RATEC; n++) {
        const ulonglong2 q0 = *(const ulonglong2*)&s_ab[n * 6 + 0];  // alpha[0..1][n]
        const ulonglong2 q1 = *(const ulonglong2*)&s_ab[n * 6 + 2];  // alpha[2..3][n]
        const u64 bn = s_ab[n * 6 + 4];                              // beta[n]
        u64 o[4];
#pragma unroll
        for (int i = 0; i < 4; i++) {
            u64 a2 = f2mul(ho[i], bn);
            a2 = f2fma(hr[0][i], q0.x, a2);
            a2 = f2fma(hr[1][i], q0.y, a2);
            a2 = f2fma(hr[2][i], q1.x, a2);
            a2 = f2fma(hr[3][i], q1.y, a2);
            o[i] = a2;
        }
        float* dst = out + hb + n * DIMC;
        stg2cs(dst + i0, o[0], o[1]);
        stg2cs(dst + i1, o[2], o[3]);
    }
}

extern "C" void kernel_launch(void* const* d_in, const int* in_sizes, int n_in,
                              void* d_out, int out_size) {
    const float* h     = (const float*)d_in[0];
    const float* h_o   = (const float*)d_in[1];
    const float* gamma = (const float*)d_in[2];
    const float* lbeta = (const float*)d_in[3];
    const float* afn   = (const float*)d_in[4];
    const float* bfn   = (const float*)d_in[5];
    const float* sA    = (const float*)d_in[6];
    const float* sB    = (const float*)d_in[7];
    float* out = (float*)d_out;

    const int ntok = in_sizes[1] / DIMC;   // b*l from h_o element count

    precompute_k<<<16, TPB>>>(gamma, lbeta, afn, bfn);
    hyper_k<<<ntok, TPB>>>(h, h_o, sA, sB, out);
}